// round 12
// baseline (speedup 1.0000x reference)
#include <cuda_runtime.h>
#include <cuda_fp16.h>
#include <cstdint>

#define NN 50000
#define NE 200000
#define DD 128
#define RR 4
#define HH 64
#define TE 64            // edge tile rows
#define TEN 32           // node tile rows
#define XSH 136          // stride (halves) for 128-wide buffers; /2 = 68 ≡ 4 mod 32
#define HSH 72           // stride (halves) for 64-wide buffers;   /2 = 36 ≡ 4 mod 32
#define NTHREADS 256
#define NSM 152

__device__ float g_acc[NN * HH];
__device__ int   g_bucket[RR * NE];
__device__ int   g_cnt[RR];

__global__ void bin_kernel(const int* __restrict__ etype) {
    __shared__ int s_cnt[RR];
    __shared__ int s_base[RR];
    int t = threadIdx.x;
    if (t < RR) s_cnt[t] = 0;
    __syncthreads();
    int e = blockIdx.x * blockDim.x + t;
    int r = -1, pos = 0;
    if (e < NE) { r = etype[e]; pos = atomicAdd(&s_cnt[r], 1); }
    __syncthreads();
    if (t < RR) s_base[t] = atomicAdd(&g_cnt[t], s_cnt[t]);
    __syncthreads();
    if (r >= 0) g_bucket[r * NE + s_base[r] + pos] = e;
}

// ---- fp16 MMA helpers -------------------------------------------------------
__device__ __forceinline__ void mma_f16(float c[4], uint32_t a0, uint32_t a1,
                                        uint32_t a2, uint32_t a3,
                                        uint32_t b0, uint32_t b1) {
    asm volatile(
        "mma.sync.aligned.m16n8k16.row.col.f32.f16.f16.f32 "
        "{%0,%1,%2,%3}, {%4,%5,%6,%7}, {%8,%9}, {%0,%1,%2,%3};"
        : "+f"(c[0]), "+f"(c[1]), "+f"(c[2]), "+f"(c[3])
        : "r"(a0), "r"(a1), "r"(a2), "r"(a3), "r"(b0), "r"(b1));
}
__device__ __forceinline__ void red2(float* p, float x, float y) {
    asm volatile("red.global.add.v2.f32 [%0], {%1, %2};"
                 :: "l"(p), "f"(x), "f"(y) : "memory");
}

// Warp GEMM over K (fp16 in, fp32 acc). act: [M][AST] halves, wT: [N][KS] halves.
// Warp covers rows mrow0..+15, cols ncol0..+8*NCH-1.
template<int K, int AST, int KS, int NCH>
__device__ __forceinline__ void wgemm(const __half* __restrict__ act,
                                      const __half* __restrict__ wT,
                                      int mrow0, int ncol0, int g, int tig,
                                      float c[NCH][4]) {
    const __half* ar0 = act + (mrow0 + g) * AST + 2 * tig;
    const __half* ar1 = ar0 + 8 * AST;
    #pragma unroll
    for (int k0 = 0; k0 < K; k0 += 16) {
        uint32_t a0 = *(const uint32_t*)(ar0 + k0);
        uint32_t a1 = *(const uint32_t*)(ar1 + k0);
        uint32_t a2 = *(const uint32_t*)(ar0 + k0 + 8);
        uint32_t a3 = *(const uint32_t*)(ar1 + k0 + 8);
        #pragma unroll
        for (int j = 0; j < NCH; j++) {
            const __half* wn = wT + (ncol0 + j * 8 + g) * KS + k0 + 2 * tig;
            uint32_t b0 = *(const uint32_t*)(wn);
            uint32_t b1 = *(const uint32_t*)(wn + 8);
            mma_f16(c[j], a0, a1, a2, a3, b0, b1);
        }
    }
}

// Epilogue: bias + relu + fp16-round, store half2 to smem [M][OST].
template<int NCH>
__device__ __forceinline__ void epi_store(float c[NCH][4], __half* outb, int OST,
                                          const float* bias, int mrow0, int ncol0,
                                          int g, int tig) {
    #pragma unroll
    for (int j = 0; j < NCH; j++) {
        int col = ncol0 + j * 8 + 2 * tig;
        float b0 = bias[col], b1 = bias[col + 1];
        *(half2*)(outb + (mrow0 + g) * OST + col) =
            __floats2half2_rn(fmaxf(c[j][0] + b0, 0.f), fmaxf(c[j][1] + b1, 0.f));
        *(half2*)(outb + (mrow0 + g + 8) * OST + col) =
            __floats2half2_rn(fmaxf(c[j][2] + b0, 0.f), fmaxf(c[j][3] + b1, 0.f));
    }
}

// SMEM layouts (byte offsets)
#define E_W1T 0
#define E_W2T (E_W1T + HH * XSH * 2)
#define E_W3T (E_W2T + HH * HSH * 2)
#define E_WNT (E_W3T + DD * HSH * 2)
#define E_SX  (E_WNT + HH * XSH * 2)
#define E_SH1 (E_SX + TE * XSH * 2)
#define E_SH2 (E_SH1 + TE * HSH * 2)
#define E_SB1 (E_SH2 + TE * HSH * 2)
#define E_SB2 (E_SB1 + HH * 4)
#define E_SB3 (E_SB2 + HH * 4)
#define E_SRC (E_SB3 + DD * 4)
#define E_DST (E_SRC + TE * 4)
#define E_TOTAL (E_DST + TE * 4)          // 99840 B -> occ 2

#define N_W1T 0
#define N_W2T (N_W1T + HH * XSH * 2)      // 17408
#define N_W3T (N_W2T + HH * HSH * 2)      // 26624
#define N_SX  (N_W3T + DD * HSH * 2)      // 45056
#define N_SH1 (N_SX + TEN * XSH * 2)      // 53760
#define N_SH2 (N_SH1 + TEN * HSH * 2)     // 58368
#define N_SB1 (N_SH2 + TEN * HSH * 2)     // 62976
#define N_SB2 (N_SB1 + HH * 4)
#define N_SB3 (N_SB2 + HH * 4)
#define N_TOTAL (N_SB3 + DD * 4)          // 64000 B -> occ 3

// ---------------------------------------------------------------------------
// Edge kernel (R5 champion, unchanged): per edge of relation r:
//   h1=relu(x@W1+b1); h2=relu(h1@W2+b2); msg=relu(h2@W3+b3);
//   p=msg@Wn1[(1+r)D:(2+r)D];  g_acc[dst] += p
// ---------------------------------------------------------------------------
__global__ __launch_bounds__(NTHREADS, 2)
void edge_kernel(const float* __restrict__ nf,
                 const int* __restrict__ esrc, const int* __restrict__ edst,
                 const float* __restrict__ Wr1, const float* __restrict__ br1,
                 const float* __restrict__ Wr2, const float* __restrict__ br2,
                 const float* __restrict__ Wr3, const float* __restrict__ br3,
                 const float* __restrict__ Wn1) {
    extern __shared__ __align__(16) char smraw[];
    __half* sW1T = (__half*)(smraw + E_W1T);   // [64][XSH]  W1^T
    __half* sW2T = (__half*)(smraw + E_W2T);   // [64][HSH]
    __half* sW3T = (__half*)(smraw + E_W3T);   // [128][HSH]
    __half* sWnT = (__half*)(smraw + E_WNT);   // [64][XSH]
    __half* sX   = (__half*)(smraw + E_SX);    // [64][XSH]  x / msg
    __half* sH1  = (__half*)(smraw + E_SH1);   // [64][HSH]
    __half* sH2  = (__half*)(smraw + E_SH2);   // [64][HSH]
    float*  sb1  = (float*)(smraw + E_SB1);
    float*  sb2  = (float*)(smraw + E_SB2);
    float*  sb3  = (float*)(smraw + E_SB3);
    int*    sSrc = (int*)(smraw + E_SRC);
    int*    sDst = (int*)(smraw + E_DST);

    const int t     = threadIdx.x;
    const int rel   = blockIdx.x & (RR - 1);
    const int bslot = blockIdx.x >> 2;
    const int nb    = gridDim.x >> 2;

    const float* gW1 = Wr1 + rel * DD * HH;
    const float* gW2 = Wr2 + rel * HH * HH;
    const float* gW3 = Wr3 + rel * HH * DD;
    const float* gWn = Wn1 + (1 + rel) * DD * HH;
    for (int i = t; i < DD * HH; i += NTHREADS) {
        int d = i >> 6, h = i & 63;
        sW1T[h * XSH + d] = __float2half(gW1[i]);
        sWnT[h * XSH + d] = __float2half(gWn[i]);
    }
    for (int i = t; i < HH * HH; i += NTHREADS) {
        int k = i >> 6, h = i & 63;
        sW2T[h * HSH + k] = __float2half(gW2[i]);
    }
    for (int i = t; i < HH * DD; i += NTHREADS) {
        int k = i >> 7, d = i & 127;
        sW3T[d * HSH + k] = __float2half(gW3[i]);
    }
    if (t < HH) { sb1[t] = br1[rel * HH + t]; sb2[t] = br2[rel * HH + t]; }
    if (t < DD) { sb3[t] = br3[rel * DD + t]; }

    const int cnt    = g_cnt[rel];
    const int ntiles = (cnt + TE - 1) / TE;

    const int lane = t & 31, w = t >> 5;
    const int g = lane >> 2, tig = lane & 3;
    const int mrow = (w & 3) * 16;
    const int nc4  = (w >> 2) * 32;
    const int nc8  = (w >> 2) * 64;
    const int grow = t >> 2, gj = t & 3;

    for (int tile = bslot; tile < ntiles; tile += nb) {
        __syncthreads();
        if (t < TE) {
            int idx = tile * TE + t;
            if (idx < cnt) {
                int e = g_bucket[rel * NE + idx];
                sSrc[t] = esrc[e];
                sDst[t] = edst[e];
            } else { sSrc[t] = 0; sDst[t] = -1; }
        }
        __syncthreads();

        // Gather x_src tile -> fp16
        {
            const float* xr = nf + (long)sSrc[grow] * DD;
            __half* dr = sX + grow * XSH;
            #pragma unroll
            for (int i = 0; i < 8; i++) {
                int d0 = gj * 4 + i * 16;
                float4 v = *(const float4*)(xr + d0);
                *(half2*)(dr + d0)     = __floats2half2_rn(v.x, v.y);
                *(half2*)(dr + d0 + 2) = __floats2half2_rn(v.z, v.w);
            }
        }
        __syncthreads();

        // L1: [64,128]@[128,64]
        {
            float c[4][4] = {};
            wgemm<DD, XSH, XSH, 4>(sX, sW1T, mrow, nc4, g, tig, c);
            epi_store<4>(c, sH1, HSH, sb1, mrow, nc4, g, tig);
        }
        __syncthreads();

        // L2: [64,64]@[64,64]
        {
            float c[4][4] = {};
            wgemm<HH, HSH, HSH, 4>(sH1, sW2T, mrow, nc4, g, tig, c);
            epi_store<4>(c, sH2, HSH, sb2, mrow, nc4, g, tig);
        }
        __syncthreads();

        // L3: [64,64]@[64,128] -> msg into sX
        {
            float c[8][4] = {};
            wgemm<HH, HSH, HSH, 8>(sH2, sW3T, mrow, nc8, g, tig, c);
            epi_store<8>(c, sX, XSH, sb3, mrow, nc8, g, tig);
        }
        __syncthreads();

        // L4: [64,128]@[128,64] -> vectorized reductions into g_acc
        {
            float c[4][4] = {};
            wgemm<DD, XSH, XSH, 4>(sX, sWnT, mrow, nc4, g, tig, c);
            int d0 = sDst[mrow + g];
            int d1 = sDst[mrow + g + 8];
            #pragma unroll
            for (int j = 0; j < 4; j++) {
                int col = nc4 + j * 8 + 2 * tig;
                if (d0 >= 0) red2(g_acc + (long)d0 * HH + col, c[j][0], c[j][1]);
                if (d1 >= 0) red2(g_acc + (long)d1 * HH + col, c[j][2], c[j][3]);
            }
        }
    }
}

// ---------------------------------------------------------------------------
// Node kernel: TEN=32 tiles, occ 3, g_acc prefetched before L1 GEMM.
//   h=relu(relu(nf)@Wn1[0:D]+g_acc+bn1); h=relu(h@Wn2+bn2); out=h@Wn3+bn3
// Warp map: mrow=(w&1)*16, n-group=(w>>1): L1/L2 NCH=2 (16 cols), L3 NCH=4 (32).
// ---------------------------------------------------------------------------
__global__ __launch_bounds__(NTHREADS, 3)
void node_kernel(const float* __restrict__ nf,
                 const float* __restrict__ Wn1, const float* __restrict__ bn1,
                 const float* __restrict__ Wn2, const float* __restrict__ bn2,
                 const float* __restrict__ Wn3, const float* __restrict__ bn3,
                 float* __restrict__ out) {
    extern __shared__ __align__(16) char smraw[];
    __half* sW1T = (__half*)(smraw + N_W1T);
    __half* sW2T = (__half*)(smraw + N_W2T);
    __half* sW3T = (__half*)(smraw + N_W3T);
    __half* sX   = (__half*)(smraw + N_SX);    // [32][XSH]
    __half* sH1  = (__half*)(smraw + N_SH1);   // [32][HSH]
    __half* sH2  = (__half*)(smraw + N_SH2);   // [32][HSH]
    float*  sb1  = (float*)(smraw + N_SB1);
    float*  sb2  = (float*)(smraw + N_SB2);
    float*  sb3  = (float*)(smraw + N_SB3);

    const int t = threadIdx.x;
    for (int i = t; i < DD * HH; i += NTHREADS) {
        int d = i >> 6, h = i & 63;
        sW1T[h * XSH + d] = __float2half(Wn1[i]);
    }
    for (int i = t; i < HH * HH; i += NTHREADS) {
        int k = i >> 6, h = i & 63;
        sW2T[h * HSH + k] = __float2half(Wn2[i]);
    }
    for (int i = t; i < HH * DD; i += NTHREADS) {
        int k = i >> 7, d = i & 127;
        sW3T[d * HSH + k] = __float2half(Wn3[i]);
    }
    if (t < HH) { sb1[t] = bn1[t]; sb2[t] = bn2[t]; }
    if (t < DD) sb3[t] = bn3[t];

    const int ntiles = (NN + TEN - 1) / TEN;
    const int lane = t & 31, w = t >> 5;
    const int g = lane >> 2, tig = lane & 3;
    const int mrow = (w & 1) * 16;       // 2 m-groups
    const int nq   = w >> 1;             // 4 n-groups
    const int nc2  = nq * 16;            // 64-col layers: NCH=2
    const int nc4n = nq * 32;            // 128-col layer: NCH=4
    const int grow = t >> 3, gj = t & 7; // gather: 8 threads per row

    for (int tile = blockIdx.x; tile < ntiles; tile += gridDim.x) {
        const int base = tile * TEN;
        __syncthreads();
        {
            const int n = base + grow;
            __half* dr = sX + grow * XSH;
            if (n < NN) {
                const float* xr = nf + (long)n * DD;
                #pragma unroll
                for (int i = 0; i < 4; i++) {
                    int d0 = gj * 4 + i * 32;
                    float4 v = *(const float4*)(xr + d0);
                    *(half2*)(dr + d0) =
                        __floats2half2_rn(fmaxf(v.x, 0.f), fmaxf(v.y, 0.f));
                    *(half2*)(dr + d0 + 2) =
                        __floats2half2_rn(fmaxf(v.z, 0.f), fmaxf(v.w, 0.f));
                }
            } else {
                #pragma unroll
                for (int i = 0; i < 4; i++) {
                    int d0 = gj * 4 + i * 32;
                    *(half2*)(dr + d0)     = __floats2half2_rn(0.f, 0.f);
                    *(half2*)(dr + d0 + 2) = __floats2half2_rn(0.f, 0.f);
                }
            }
        }
        __syncthreads();

        const int n0 = base + mrow + g;
        const int n1 = n0 + 8;

        // Prefetch g_acc BEFORE the L1 GEMM so the global latency hides
        // behind the MMAs.
        float2 ga[2][2];
        #pragma unroll
        for (int j = 0; j < 2; j++) {
            int col = nc2 + j * 8 + 2 * tig;
            ga[j][0] = (n0 < NN) ? *(const float2*)(g_acc + (long)n0 * HH + col)
                                 : make_float2(0.f, 0.f);
            ga[j][1] = (n1 < NN) ? *(const float2*)(g_acc + (long)n1 * HH + col)
                                 : make_float2(0.f, 0.f);
        }

        // L1 + g_acc + bias
        {
            float c[2][4] = {};
            wgemm<DD, XSH, XSH, 2>(sX, sW1T, mrow, nc2, g, tig, c);
            #pragma unroll
            for (int j = 0; j < 2; j++) {
                int col = nc2 + j * 8 + 2 * tig;
                float b0 = sb1[col], b1 = sb1[col + 1];
                *(half2*)(sH1 + (mrow + g) * HSH + col) = __floats2half2_rn(
                    fmaxf(c[j][0] + ga[j][0].x + b0, 0.f),
                    fmaxf(c[j][1] + ga[j][0].y + b1, 0.f));
                *(half2*)(sH1 + (mrow + g + 8) * HSH + col) = __floats2half2_rn(
                    fmaxf(c[j][2] + ga[j][1].x + b0, 0.f),
                    fmaxf(c[j][3] + ga[j][1].y + b1, 0.f));
            }
        }
        __syncthreads();

        // L2
        {
            float c[2][4] = {};
            wgemm<HH, HSH, HSH, 2>(sH1, sW2T, mrow, nc2, g, tig, c);
            epi_store<2>(c, sH2, HSH, sb2, mrow, nc2, g, tig);
        }
        __syncthreads();

        // L3 -> out (fp32)
        {
            float c[4][4] = {};
            wgemm<HH, HSH, HSH, 4>(sH2, sW3T, mrow, nc4n, g, tig, c);
            #pragma unroll
            for (int j = 0; j < 4; j++) {
                int col = nc4n + j * 8 + 2 * tig;
                float b0 = sb3[col], b1 = sb3[col + 1];
                if (n0 < NN) {
                    float2 v; v.x = c[j][0] + b0; v.y = c[j][1] + b1;
                    *(float2*)(out + (long)n0 * DD + col) = v;
                }
                if (n1 < NN) {
                    float2 v; v.x = c[j][2] + b0; v.y = c[j][3] + b1;
                    *(float2*)(out + (long)n1 * DD + col) = v;
                }
            }
        }
        __syncthreads();
    }
}

extern "C" void kernel_launch(void* const* d_in, const int* in_sizes, int n_in,
                              void* d_out, int out_size) {
    const float* nf   = (const float*)d_in[0];
    const int*   esrc = (const int*)d_in[1];
    const int*   edst = (const int*)d_in[2];
    const int*   etyp = (const int*)d_in[3];
    const float* Wr1  = (const float*)d_in[4];
    const float* br1  = (const float*)d_in[5];
    const float* Wr2  = (const float*)d_in[6];
    const float* br2  = (const float*)d_in[7];
    const float* Wr3  = (const float*)d_in[8];
    const float* br3  = (const float*)d_in[9];
    const float* Wn1  = (const float*)d_in[10];
    const float* bn1  = (const float*)d_in[11];
    const float* Wn2  = (const float*)d_in[12];
    const float* bn2  = (const float*)d_in[13];
    const float* Wn3  = (const float*)d_in[14];
    const float* bn3  = (const float*)d_in[15];
    float* out = (float*)d_out;

    cudaFuncSetAttribute(edge_kernel, cudaFuncAttributeMaxDynamicSharedMemorySize, E_TOTAL);
    cudaFuncSetAttribute(node_kernel, cudaFuncAttributeMaxDynamicSharedMemorySize, N_TOTAL);

    void* accp = nullptr; void* cntp = nullptr;
    cudaGetSymbolAddress(&accp, g_acc);
    cudaGetSymbolAddress(&cntp, g_cnt);
    cudaMemsetAsync(accp, 0, (size_t)NN * HH * sizeof(float));
    cudaMemsetAsync(cntp, 0, RR * sizeof(int));

    bin_kernel<<<(NE + NTHREADS - 1) / NTHREADS, NTHREADS>>>(etyp);
    edge_kernel<<<2 * NSM, NTHREADS, E_TOTAL>>>(nf, esrc, edst,
                                                Wr1, br1, Wr2, br2, Wr3, br3, Wn1);
    node_kernel<<<3 * NSM, NTHREADS, N_TOTAL>>>(nf, Wn1, bn1, Wn2, bn2, Wn3, bn3, out);
}

// round 13
// speedup vs baseline: 1.0433x; 1.0433x over previous
#include <cuda_runtime.h>
#include <cuda_fp16.h>
#include <cstdint>

#define NN 50000
#define NE 200000
#define DD 128
#define RR 4
#define HH 64
#define TE 64            // rows (edges/nodes) per tile (M)
#define XSH 136          // stride (halves) for 128-wide buffers; /2 = 68 ≡ 4 mod 32
#define HSH 72           // stride (halves) for 64-wide buffers;   /2 = 36 ≡ 4 mod 32
#define NTHREADS 256
#define NSM 152

__device__ float g_acc[NN * HH];
__device__ int   g_bucket[RR * NE];
__device__ int   g_cnt[RR];

__global__ void bin_kernel(const int* __restrict__ etype) {
    __shared__ int s_cnt[RR];
    __shared__ int s_base[RR];
    int t = threadIdx.x;
    if (t < RR) s_cnt[t] = 0;
    __syncthreads();
    int e = blockIdx.x * blockDim.x + t;
    int r = -1, pos = 0;
    if (e < NE) { r = etype[e]; pos = atomicAdd(&s_cnt[r], 1); }
    __syncthreads();
    if (t < RR) s_base[t] = atomicAdd(&g_cnt[t], s_cnt[t]);
    __syncthreads();
    if (r >= 0) g_bucket[r * NE + s_base[r] + pos] = e;
}

// ---- fp16 MMA helpers -------------------------------------------------------
__device__ __forceinline__ void mma_f16(float c[4], uint32_t a0, uint32_t a1,
                                        uint32_t a2, uint32_t a3,
                                        uint32_t b0, uint32_t b1) {
    asm volatile(
        "mma.sync.aligned.m16n8k16.row.col.f32.f16.f16.f32 "
        "{%0,%1,%2,%3}, {%4,%5,%6,%7}, {%8,%9}, {%0,%1,%2,%3};"
        : "+f"(c[0]), "+f"(c[1]), "+f"(c[2]), "+f"(c[3])
        : "r"(a0), "r"(a1), "r"(a2), "r"(a3), "r"(b0), "r"(b1));
}
__device__ __forceinline__ void red2(float* p, float x, float y) {
    asm volatile("red.global.add.v2.f32 [%0], {%1, %2};"
                 :: "l"(p), "f"(x), "f"(y) : "memory");
}

// Warp GEMM over K (fp16 in, fp32 acc). act: [M][AST] halves, wT: [N][KS] halves.
template<int K, int AST, int KS, int NCH>
__device__ __forceinline__ void wgemm(const __half* __restrict__ act,
                                      const __half* __restrict__ wT,
                                      int mrow0, int ncol0, int g, int tig,
                                      float c[NCH][4]) {
    const __half* ar0 = act + (mrow0 + g) * AST + 2 * tig;
    const __half* ar1 = ar0 + 8 * AST;
    #pragma unroll
    for (int k0 = 0; k0 < K; k0 += 16) {
        uint32_t a0 = *(const uint32_t*)(ar0 + k0);
        uint32_t a1 = *(const uint32_t*)(ar1 + k0);
        uint32_t a2 = *(const uint32_t*)(ar0 + k0 + 8);
        uint32_t a3 = *(const uint32_t*)(ar1 + k0 + 8);
        #pragma unroll
        for (int j = 0; j < NCH; j++) {
            const __half* wn = wT + (ncol0 + j * 8 + g) * KS + k0 + 2 * tig;
            uint32_t b0 = *(const uint32_t*)(wn);
            uint32_t b1 = *(const uint32_t*)(wn + 8);
            mma_f16(c[j], a0, a1, a2, a3, b0, b1);
        }
    }
}

// Epilogue: bias + relu + fp16-round, store half2 to smem [M][OST].
template<int NCH>
__device__ __forceinline__ void epi_store(float c[NCH][4], __half* outb, int OST,
                                          const float* bias, int mrow0, int ncol0,
                                          int g, int tig) {
    #pragma unroll
    for (int j = 0; j < NCH; j++) {
        int col = ncol0 + j * 8 + 2 * tig;
        float b0 = bias[col], b1 = bias[col + 1];
        *(half2*)(outb + (mrow0 + g) * OST + col) =
            __floats2half2_rn(fmaxf(c[j][0] + b0, 0.f), fmaxf(c[j][1] + b1, 0.f));
        *(half2*)(outb + (mrow0 + g + 8) * OST + col) =
            __floats2half2_rn(fmaxf(c[j][2] + b0, 0.f), fmaxf(c[j][3] + b1, 0.f));
    }
}

// SMEM layouts (byte offsets)
#define E_W1T 0
#define E_W2T (E_W1T + HH * XSH * 2)
#define E_W3T (E_W2T + HH * HSH * 2)
#define E_WNT (E_W3T + DD * HSH * 2)
#define E_SX  (E_WNT + HH * XSH * 2)
#define E_SH1 (E_SX + TE * XSH * 2)
#define E_SH2 (E_SH1 + TE * HSH * 2)
#define E_SB1 (E_SH2 + TE * HSH * 2)
#define E_SB2 (E_SB1 + HH * 4)
#define E_SB3 (E_SB2 + HH * 4)
#define E_DST (E_SB3 + DD * 4)
#define E_TOTAL (E_DST + TE * 4)          // ~99.6 KB -> occ 2

#define N_W1T 0
#define N_W2T (N_W1T + HH * XSH * 2)
#define N_W3T (N_W2T + HH * HSH * 2)
#define N_SX  (N_W3T + DD * HSH * 2)
#define N_SH1 (N_SX + TE * XSH * 2)
#define N_SH2 (N_SH1 + TE * HSH * 2)
#define N_SB1 (N_SH2 + TE * HSH * 2)
#define N_SB2 (N_SB1 + HH * 4)
#define N_SB3 (N_SB2 + HH * 4)
#define N_TOTAL (N_SB3 + DD * 4)          // 81920 B -> occ 2

// ---------------------------------------------------------------------------
// Edge kernel with cross-tile prefetch of the gather chain.
// ---------------------------------------------------------------------------
__global__ __launch_bounds__(NTHREADS, 2)
void edge_kernel(const float* __restrict__ nf,
                 const int* __restrict__ esrc, const int* __restrict__ edst,
                 const float* __restrict__ Wr1, const float* __restrict__ br1,
                 const float* __restrict__ Wr2, const float* __restrict__ br2,
                 const float* __restrict__ Wr3, const float* __restrict__ br3,
                 const float* __restrict__ Wn1) {
    extern __shared__ __align__(16) char smraw[];
    __half* sW1T = (__half*)(smraw + E_W1T);   // [64][XSH]  W1^T
    __half* sW2T = (__half*)(smraw + E_W2T);   // [64][HSH]
    __half* sW3T = (__half*)(smraw + E_W3T);   // [128][HSH]
    __half* sWnT = (__half*)(smraw + E_WNT);   // [64][XSH]
    __half* sX   = (__half*)(smraw + E_SX);    // [64][XSH]  x / msg
    __half* sH1  = (__half*)(smraw + E_SH1);   // [64][HSH]
    __half* sH2  = (__half*)(smraw + E_SH2);   // [64][HSH]
    float*  sb1  = (float*)(smraw + E_SB1);
    float*  sb2  = (float*)(smraw + E_SB2);
    float*  sb3  = (float*)(smraw + E_SB3);
    int*    sDst = (int*)(smraw + E_DST);

    const int t     = threadIdx.x;
    const int rel   = blockIdx.x & (RR - 1);
    const int bslot = blockIdx.x >> 2;
    const int nb    = gridDim.x >> 2;

    const float* gW1 = Wr1 + rel * DD * HH;
    const float* gW2 = Wr2 + rel * HH * HH;
    const float* gW3 = Wr3 + rel * HH * DD;
    const float* gWn = Wn1 + (1 + rel) * DD * HH;
    for (int i = t; i < DD * HH; i += NTHREADS) {
        int d = i >> 6, h = i & 63;
        sW1T[h * XSH + d] = __float2half(gW1[i]);
        sWnT[h * XSH + d] = __float2half(gWn[i]);
    }
    for (int i = t; i < HH * HH; i += NTHREADS) {
        int k = i >> 6, h = i & 63;
        sW2T[h * HSH + k] = __float2half(gW2[i]);
    }
    for (int i = t; i < HH * DD; i += NTHREADS) {
        int k = i >> 7, d = i & 127;
        sW3T[d * HSH + k] = __float2half(gW3[i]);
    }
    if (t < HH) { sb1[t] = br1[rel * HH + t]; sb2[t] = br2[rel * HH + t]; }
    if (t < DD) { sb3[t] = br3[rel * DD + t]; }

    const int cnt    = g_cnt[rel];
    const int ntiles = (cnt + TE - 1) / TE;

    const int lane = t & 31, w = t >> 5;
    const int g = lane >> 2, tig = lane & 3;
    const int mrow = (w & 3) * 16;
    const int nc4  = (w >> 2) * 32;
    const int nc8  = (w >> 2) * 64;
    const int grow = t >> 2, gj = t & 3;
    const int* gb = g_bucket + rel * NE;

    // prefetch state: this thread serves row `grow` of the tile
    float4 xreg[8];
    int dreg = -1;

    auto prefetch = [&](int tl) {
        int idxr = tl * TE + grow;
        int src = 0; dreg = -1;
        if (idxr < cnt) {
            int e = gb[idxr];
            src = esrc[e];
            dreg = edst[e];
        }
        const float* xp = nf + (long)src * DD;
        #pragma unroll
        for (int i = 0; i < 8; i++)
            xreg[i] = *(const float4*)(xp + gj * 4 + i * 16);
    };

    if (bslot < ntiles) prefetch(bslot);

    for (int tile = bslot; tile < ntiles; tile += nb) {
        __syncthreads();             // sX / sDst free (prev L4 done)
        // stage prefetched x -> sX; one thread per row writes sDst
        {
            __half* dr = sX + grow * XSH;
            #pragma unroll
            for (int i = 0; i < 8; i++) {
                int d0 = gj * 4 + i * 16;
                *(half2*)(dr + d0)     = __floats2half2_rn(xreg[i].x, xreg[i].y);
                *(half2*)(dr + d0 + 2) = __floats2half2_rn(xreg[i].z, xreg[i].w);
            }
            if (gj == 0) sDst[grow] = dreg;
        }
        __syncthreads();

        // L1: [64,128]@[128,64]
        {
            float c[4][4] = {};
            wgemm<DD, XSH, XSH, 4>(sX, sW1T, mrow, nc4, g, tig, c);
            epi_store<4>(c, sH1, HSH, sb1, mrow, nc4, g, tig);
        }
        __syncthreads();

        // L2: [64,64]@[64,64]
        {
            float c[4][4] = {};
            wgemm<HH, HSH, HSH, 4>(sH1, sW2T, mrow, nc4, g, tig, c);
            epi_store<4>(c, sH2, HSH, sb2, mrow, nc4, g, tig);
        }
        __syncthreads();

        // L3: [64,64]@[64,128] -> msg into sX
        {
            float c[8][4] = {};
            wgemm<HH, HSH, HSH, 8>(sH2, sW3T, mrow, nc8, g, tig, c);
            epi_store<8>(c, sX, XSH, sb3, mrow, nc8, g, tig);
        }
        __syncthreads();

        // prefetch next tile's gather chain; hides behind L4 + reductions
        if (tile + nb < ntiles) prefetch(tile + nb);

        // L4: [64,128]@[128,64] -> reductions into g_acc
        {
            float c[4][4] = {};
            wgemm<DD, XSH, XSH, 4>(sX, sWnT, mrow, nc4, g, tig, c);
            int d0 = sDst[mrow + g];
            int d1 = sDst[mrow + g + 8];
            #pragma unroll
            for (int j = 0; j < 4; j++) {
                int col = nc4 + j * 8 + 2 * tig;
                if (d0 >= 0) red2(g_acc + (long)d0 * HH + col, c[j][0], c[j][1]);
                if (d1 >= 0) red2(g_acc + (long)d1 * HH + col, c[j][2], c[j][3]);
            }
        }
    }
}

// ---------------------------------------------------------------------------
// Node kernel (R5 geometry) with cross-tile prefetch of x and g_acc.
// ---------------------------------------------------------------------------
__global__ __launch_bounds__(NTHREADS, 2)
void node_kernel(const float* __restrict__ nf,
                 const float* __restrict__ Wn1, const float* __restrict__ bn1,
                 const float* __restrict__ Wn2, const float* __restrict__ bn2,
                 const float* __restrict__ Wn3, const float* __restrict__ bn3,
                 float* __restrict__ out) {
    extern __shared__ __align__(16) char smraw[];
    __half* sW1T = (__half*)(smraw + N_W1T);
    __half* sW2T = (__half*)(smraw + N_W2T);
    __half* sW3T = (__half*)(smraw + N_W3T);
    __half* sX   = (__half*)(smraw + N_SX);
    __half* sH1  = (__half*)(smraw + N_SH1);
    __half* sH2  = (__half*)(smraw + N_SH2);
    float*  sb1  = (float*)(smraw + N_SB1);
    float*  sb2  = (float*)(smraw + N_SB2);
    float*  sb3  = (float*)(smraw + N_SB3);

    const int t = threadIdx.x;
    for (int i = t; i < DD * HH; i += NTHREADS) {
        int d = i >> 6, h = i & 63;
        sW1T[h * XSH + d] = __float2half(Wn1[i]);
    }
    for (int i = t; i < HH * HH; i += NTHREADS) {
        int k = i >> 6, h = i & 63;
        sW2T[h * HSH + k] = __float2half(Wn2[i]);
    }
    for (int i = t; i < HH * DD; i += NTHREADS) {
        int k = i >> 7, d = i & 127;
        sW3T[d * HSH + k] = __float2half(Wn3[i]);
    }
    if (t < HH) { sb1[t] = bn1[t]; sb2[t] = bn2[t]; }
    if (t < DD) sb3[t] = bn3[t];

    const int ntiles = (NN + TE - 1) / TE;
    const int lane = t & 31, w = t >> 5;
    const int g = lane >> 2, tig = lane & 3;
    const int mrow = (w & 3) * 16;
    const int nc4  = (w >> 2) * 32;
    const int nc8  = (w >> 2) * 64;
    const int grow = t >> 2, gj = t & 3;

    float4 xreg[8];
    float2 ga[4][2];

    auto prefetch = [&](int tl) {
        const int n = tl * TE + grow;
        if (n < NN) {
            const float* xr = nf + (long)n * DD;
            #pragma unroll
            for (int i = 0; i < 8; i++)
                xreg[i] = *(const float4*)(xr + gj * 4 + i * 16);
        } else {
            #pragma unroll
            for (int i = 0; i < 8; i++)
                xreg[i] = make_float4(0.f, 0.f, 0.f, 0.f);
        }
        const int n0 = tl * TE + mrow + g;
        const int n1 = n0 + 8;
        #pragma unroll
        for (int j = 0; j < 4; j++) {
            int col = nc4 + j * 8 + 2 * tig;
            ga[j][0] = (n0 < NN) ? *(const float2*)(g_acc + (long)n0 * HH + col)
                                 : make_float2(0.f, 0.f);
            ga[j][1] = (n1 < NN) ? *(const float2*)(g_acc + (long)n1 * HH + col)
                                 : make_float2(0.f, 0.f);
        }
    };

    if (blockIdx.x < ntiles) prefetch(blockIdx.x);

    for (int tile = blockIdx.x; tile < ntiles; tile += gridDim.x) {
        const int base = tile * TE;
        __syncthreads();            // sX free
        {
            __half* dr = sX + grow * XSH;
            #pragma unroll
            for (int i = 0; i < 8; i++) {
                int d0 = gj * 4 + i * 16;
                *(half2*)(dr + d0) = __floats2half2_rn(fmaxf(xreg[i].x, 0.f),
                                                       fmaxf(xreg[i].y, 0.f));
                *(half2*)(dr + d0 + 2) = __floats2half2_rn(fmaxf(xreg[i].z, 0.f),
                                                           fmaxf(xreg[i].w, 0.f));
            }
        }
        __syncthreads();

        const int n0 = base + mrow + g;
        const int n1 = n0 + 8;

        // L1 + g_acc (prefetched) + bias
        {
            float c[4][4] = {};
            wgemm<DD, XSH, XSH, 4>(sX, sW1T, mrow, nc4, g, tig, c);
            #pragma unroll
            for (int j = 0; j < 4; j++) {
                int col = nc4 + j * 8 + 2 * tig;
                float b0 = sb1[col], b1 = sb1[col + 1];
                *(half2*)(sH1 + (mrow + g) * HSH + col) =
                    (n0 < NN) ? __floats2half2_rn(fmaxf(c[j][0] + ga[j][0].x + b0, 0.f),
                                                  fmaxf(c[j][1] + ga[j][0].y + b1, 0.f))
                              : __floats2half2_rn(0.f, 0.f);
                *(half2*)(sH1 + (mrow + g + 8) * HSH + col) =
                    (n1 < NN) ? __floats2half2_rn(fmaxf(c[j][2] + ga[j][1].x + b0, 0.f),
                                                  fmaxf(c[j][3] + ga[j][1].y + b1, 0.f))
                              : __floats2half2_rn(0.f, 0.f);
            }
        }
        __syncthreads();

        // L2
        {
            float c[4][4] = {};
            wgemm<HH, HSH, HSH, 4>(sH1, sW2T, mrow, nc4, g, tig, c);
            epi_store<4>(c, sH2, HSH, sb2, mrow, nc4, g, tig);
        }
        __syncthreads();

        // prefetch next tile (hides behind L3 + output stores)
        if (tile + gridDim.x < ntiles) prefetch(tile + gridDim.x);

        // L3 -> out (fp32)
        {
            float c[8][4] = {};
            wgemm<HH, HSH, HSH, 8>(sH2, sW3T, mrow, nc8, g, tig, c);
            #pragma unroll
            for (int j = 0; j < 8; j++) {
                int col = nc8 + j * 8 + 2 * tig;
                float b0 = sb3[col], b1 = sb3[col + 1];
                if (n0 < NN) {
                    float2 v; v.x = c[j][0] + b0; v.y = c[j][1] + b1;
                    *(float2*)(out + (long)n0 * DD + col) = v;
                }
                if (n1 < NN) {
                    float2 v; v.x = c[j][2] + b0; v.y = c[j][3] + b1;
                    *(float2*)(out + (long)n1 * DD + col) = v;
                }
            }
        }
    }
}

extern "C" void kernel_launch(void* const* d_in, const int* in_sizes, int n_in,
                              void* d_out, int out_size) {
    const float* nf   = (const float*)d_in[0];
    const int*   esrc = (const int*)d_in[1];
    const int*   edst = (const int*)d_in[2];
    const int*   etyp = (const int*)d_in[3];
    const float* Wr1  = (const float*)d_in[4];
    const float* br1  = (const float*)d_in[5];
    const float* Wr2  = (const float*)d_in[6];
    const float* br2  = (const float*)d_in[7];
    const float* Wr3  = (const float*)d_in[8];
    const float* br3  = (const float*)d_in[9];
    const float* Wn1  = (const float*)d_in[10];
    const float* bn1  = (const float*)d_in[11];
    const float* Wn2  = (const float*)d_in[12];
    const float* bn2  = (const float*)d_in[13];
    const float* Wn3  = (const float*)d_in[14];
    const float* bn3  = (const float*)d_in[15];
    float* out = (float*)d_out;

    cudaFuncSetAttribute(edge_kernel, cudaFuncAttributeMaxDynamicSharedMemorySize, E_TOTAL);
    cudaFuncSetAttribute(node_kernel, cudaFuncAttributeMaxDynamicSharedMemorySize, N_TOTAL);

    void* accp = nullptr; void* cntp = nullptr;
    cudaGetSymbolAddress(&accp, g_acc);
    cudaGetSymbolAddress(&cntp, g_cnt);
    cudaMemsetAsync(accp, 0, (size_t)NN * HH * sizeof(float));
    cudaMemsetAsync(cntp, 0, RR * sizeof(int));

    bin_kernel<<<(NE + NTHREADS - 1) / NTHREADS, NTHREADS>>>(etyp);
    edge_kernel<<<2 * NSM, NTHREADS, E_TOTAL>>>(nf, esrc, edst,
                                                Wr1, br1, Wr2, br2, Wr3, br3, Wn1);
    node_kernel<<<2 * NSM, NTHREADS, N_TOTAL>>>(nf, Wn1, bn1, Wn2, bn2, Wn3, bn3, out);
}

// round 14
// speedup vs baseline: 1.1455x; 1.0980x over previous
#include <cuda_runtime.h>
#include <cuda_fp16.h>
#include <cstdint>

#define NN 50000
#define NE 200000
#define DD 128
#define RR 4
#define HH 64
#define TE 64            // rows (edges/nodes) per tile (M)
#define XSH 136          // stride (halves) for 128-wide buffers; /2 = 68 ≡ 4 mod 32
#define HSH 72           // stride (halves) for 64-wide buffers;   /2 = 36 ≡ 4 mod 32
#define NTHREADS 256
#define NSM 152

__device__ float g_acc[NN * HH];
__device__ int   g_bucket[RR * NE];
__device__ int   g_cnt[RR];

// Ballot-based binning: 4 smem atomics per warp, 4 global atomics per block.
__global__ void bin_kernel(const int* __restrict__ etype) {
    __shared__ int s_cnt[RR];
    __shared__ int s_base[RR];
    __shared__ int w_base[8][RR];
    const int t = threadIdx.x, wid = t >> 5, lane = t & 31;
    if (t < RR) s_cnt[t] = 0;
    __syncthreads();
    int e = blockIdx.x * blockDim.x + t;
    bool act = e < NE;
    int r = act ? etype[e] : -1;
    int rank = 0;
    #pragma unroll
    for (int rel = 0; rel < RR; rel++) {
        unsigned mask = __ballot_sync(0xffffffffu, r == rel);
        if (lane == 0) w_base[wid][rel] = mask ? atomicAdd(&s_cnt[rel], __popc(mask)) : 0;
        if (r == rel) rank = __popc(mask & ((1u << lane) - 1));
    }
    __syncthreads();
    if (t < RR) s_base[t] = atomicAdd(&g_cnt[t], s_cnt[t]);
    __syncthreads();
    if (act) g_bucket[r * NE + s_base[r] + w_base[wid][r] + rank] = e;
}

// ---- fp16 MMA helpers -------------------------------------------------------
__device__ __forceinline__ void mma_f16(float c[4], uint32_t a0, uint32_t a1,
                                        uint32_t a2, uint32_t a3,
                                        uint32_t b0, uint32_t b1) {
    asm volatile(
        "mma.sync.aligned.m16n8k16.row.col.f32.f16.f16.f32 "
        "{%0,%1,%2,%3}, {%4,%5,%6,%7}, {%8,%9}, {%0,%1,%2,%3};"
        : "+f"(c[0]), "+f"(c[1]), "+f"(c[2]), "+f"(c[3])
        : "r"(a0), "r"(a1), "r"(a2), "r"(a3), "r"(b0), "r"(b1));
}
__device__ __forceinline__ void red2(float* p, float x, float y) {
    asm volatile("red.global.add.v2.f32 [%0], {%1, %2};"
                 :: "l"(p), "f"(x), "f"(y) : "memory");
}

// Vectorized transposed weight loaders: src [K][Nsrc] row-major f32,
// dst [Nsrc rows][DSTST] halves (K contiguous per row is FALSE here —
// dst row = src column). Each thread: 4 coalesced LDG + one 8B STS.
// W1/Wn style: src [DD][HH] -> dst[h][d], DSTST=XSH
__device__ __forceinline__ void load_wT_128x64(const float* __restrict__ src,
                                               __half* __restrict__ dst, int t) {
    const int h = t & 63, dg = (t >> 6) & 3;
    #pragma unroll
    for (int base = 0; base < DD; base += 16) {
        int d0 = base + dg * 4;
        float a0 = src[(d0 + 0) * HH + h];
        float a1 = src[(d0 + 1) * HH + h];
        float a2 = src[(d0 + 2) * HH + h];
        float a3 = src[(d0 + 3) * HH + h];
        *(half2*)(dst + h * XSH + d0)     = __floats2half2_rn(a0, a1);
        *(half2*)(dst + h * XSH + d0 + 2) = __floats2half2_rn(a2, a3);
    }
}
// W2 style: src [HH][HH] -> dst[h][k], DSTST=HSH
__device__ __forceinline__ void load_wT_64x64(const float* __restrict__ src,
                                              __half* __restrict__ dst, int t) {
    const int h = t & 63, kg = (t >> 6) & 3;
    #pragma unroll
    for (int base = 0; base < HH; base += 16) {
        int k0 = base + kg * 4;
        float a0 = src[(k0 + 0) * HH + h];
        float a1 = src[(k0 + 1) * HH + h];
        float a2 = src[(k0 + 2) * HH + h];
        float a3 = src[(k0 + 3) * HH + h];
        *(half2*)(dst + h * HSH + k0)     = __floats2half2_rn(a0, a1);
        *(half2*)(dst + h * HSH + k0 + 2) = __floats2half2_rn(a2, a3);
    }
}
// W3 style: src [HH][DD] -> dst[d][k], DSTST=HSH (128 rows)
__device__ __forceinline__ void load_wT_64x128(const float* __restrict__ src,
                                               __half* __restrict__ dst, int t) {
    const int d = t & 127, kg = (t >> 7) & 1;
    #pragma unroll
    for (int base = 0; base < HH; base += 8) {
        int k0 = base + kg * 4;
        float a0 = src[(k0 + 0) * DD + d];
        float a1 = src[(k0 + 1) * DD + d];
        float a2 = src[(k0 + 2) * DD + d];
        float a3 = src[(k0 + 3) * DD + d];
        *(half2*)(dst + d * HSH + k0)     = __floats2half2_rn(a0, a1);
        *(half2*)(dst + d * HSH + k0 + 2) = __floats2half2_rn(a2, a3);
    }
}

// Warp GEMM over K (fp16 in, fp32 acc). act: [M][AST] halves, wT: [N][KS] halves.
template<int K, int AST, int KS, int NCH>
__device__ __forceinline__ void wgemm(const __half* __restrict__ act,
                                      const __half* __restrict__ wT,
                                      int mrow0, int ncol0, int g, int tig,
                                      float c[NCH][4]) {
    const __half* ar0 = act + (mrow0 + g) * AST + 2 * tig;
    const __half* ar1 = ar0 + 8 * AST;
    #pragma unroll
    for (int k0 = 0; k0 < K; k0 += 16) {
        uint32_t a0 = *(const uint32_t*)(ar0 + k0);
        uint32_t a1 = *(const uint32_t*)(ar1 + k0);
        uint32_t a2 = *(const uint32_t*)(ar0 + k0 + 8);
        uint32_t a3 = *(const uint32_t*)(ar1 + k0 + 8);
        #pragma unroll
        for (int j = 0; j < NCH; j++) {
            const __half* wn = wT + (ncol0 + j * 8 + g) * KS + k0 + 2 * tig;
            uint32_t b0 = *(const uint32_t*)(wn);
            uint32_t b1 = *(const uint32_t*)(wn + 8);
            mma_f16(c[j], a0, a1, a2, a3, b0, b1);
        }
    }
}

// Epilogue: bias + relu + fp16-round, store half2 to smem [M][OST].
template<int NCH>
__device__ __forceinline__ void epi_store(float c[NCH][4], __half* outb, int OST,
                                          const float* bias, int mrow0, int ncol0,
                                          int g, int tig) {
    #pragma unroll
    for (int j = 0; j < NCH; j++) {
        int col = ncol0 + j * 8 + 2 * tig;
        float b0 = bias[col], b1 = bias[col + 1];
        *(half2*)(outb + (mrow0 + g) * OST + col) =
            __floats2half2_rn(fmaxf(c[j][0] + b0, 0.f), fmaxf(c[j][1] + b1, 0.f));
        *(half2*)(outb + (mrow0 + g + 8) * OST + col) =
            __floats2half2_rn(fmaxf(c[j][2] + b0, 0.f), fmaxf(c[j][3] + b1, 0.f));
    }
}

// SMEM layouts (byte offsets)
#define E_W1T 0
#define E_W2T (E_W1T + HH * XSH * 2)
#define E_W3T (E_W2T + HH * HSH * 2)
#define E_WNT (E_W3T + DD * HSH * 2)
#define E_SX  (E_WNT + HH * XSH * 2)
#define E_SH1 (E_SX + TE * XSH * 2)
#define E_SH2 (E_SH1 + TE * HSH * 2)
#define E_SB1 (E_SH2 + TE * HSH * 2)
#define E_SB2 (E_SB1 + HH * 4)
#define E_SB3 (E_SB2 + HH * 4)
#define E_DST (E_SB3 + DD * 4)
#define E_TOTAL (E_DST + TE * 4)          // ~99.6 KB -> occ 2

#define N_W1T 0
#define N_W2T (N_W1T + HH * XSH * 2)
#define N_W3T (N_W2T + HH * HSH * 2)
#define N_SX  (N_W3T + DD * HSH * 2)
#define N_SH1 (N_SX + TE * XSH * 2)
#define N_SH2 (N_SH1 + TE * HSH * 2)
#define N_SB1 (N_SH2 + TE * HSH * 2)
#define N_SB2 (N_SB1 + HH * 4)
#define N_SB3 (N_SB2 + HH * 4)
#define N_TOTAL (N_SB3 + DD * 4)          // 81920 B -> occ 2

// ---------------------------------------------------------------------------
// Edge kernel with cross-tile prefetch of the gather chain.
// ---------------------------------------------------------------------------
__global__ __launch_bounds__(NTHREADS, 2)
void edge_kernel(const float* __restrict__ nf,
                 const int* __restrict__ esrc, const int* __restrict__ edst,
                 const float* __restrict__ Wr1, const float* __restrict__ br1,
                 const float* __restrict__ Wr2, const float* __restrict__ br2,
                 const float* __restrict__ Wr3, const float* __restrict__ br3,
                 const float* __restrict__ Wn1) {
    extern __shared__ __align__(16) char smraw[];
    __half* sW1T = (__half*)(smraw + E_W1T);   // [64][XSH]  W1^T
    __half* sW2T = (__half*)(smraw + E_W2T);   // [64][HSH]
    __half* sW3T = (__half*)(smraw + E_W3T);   // [128][HSH]
    __half* sWnT = (__half*)(smraw + E_WNT);   // [64][XSH]
    __half* sX   = (__half*)(smraw + E_SX);    // [64][XSH]  x / msg
    __half* sH1  = (__half*)(smraw + E_SH1);   // [64][HSH]
    __half* sH2  = (__half*)(smraw + E_SH2);   // [64][HSH]
    float*  sb1  = (float*)(smraw + E_SB1);
    float*  sb2  = (float*)(smraw + E_SB2);
    float*  sb3  = (float*)(smraw + E_SB3);
    int*    sDst = (int*)(smraw + E_DST);

    const int t     = threadIdx.x;
    const int rel   = blockIdx.x & (RR - 1);
    const int bslot = blockIdx.x >> 2;
    const int nb    = gridDim.x >> 2;

    load_wT_128x64(Wr1 + rel * DD * HH, sW1T, t);
    load_wT_128x64(Wn1 + (1 + rel) * DD * HH, sWnT, t);
    load_wT_64x64(Wr2 + rel * HH * HH, sW2T, t);
    load_wT_64x128(Wr3 + rel * HH * DD, sW3T, t);
    if (t < HH) { sb1[t] = br1[rel * HH + t]; sb2[t] = br2[rel * HH + t]; }
    if (t < DD) { sb3[t] = br3[rel * DD + t]; }

    const int cnt    = g_cnt[rel];
    const int ntiles = (cnt + TE - 1) / TE;

    const int lane = t & 31, w = t >> 5;
    const int g = lane >> 2, tig = lane & 3;
    const int mrow = (w & 3) * 16;
    const int nc4  = (w >> 2) * 32;
    const int nc8  = (w >> 2) * 64;
    const int grow = t >> 2, gj = t & 3;
    const int* gb = g_bucket + rel * NE;

    float4 xreg[8];
    int dreg = -1;

    auto prefetch = [&](int tl) {
        int idxr = tl * TE + grow;
        int src = 0; dreg = -1;
        if (idxr < cnt) {
            int e = gb[idxr];
            src = esrc[e];
            dreg = edst[e];
        }
        const float* xp = nf + (long)src * DD;
        #pragma unroll
        for (int i = 0; i < 8; i++)
            xreg[i] = *(const float4*)(xp + gj * 4 + i * 16);
    };

    if (bslot < ntiles) prefetch(bslot);

    for (int tile = bslot; tile < ntiles; tile += nb) {
        __syncthreads();             // sX / sDst free (prev L4 done); also weights on iter 0
        {
            __half* dr = sX + grow * XSH;
            #pragma unroll
            for (int i = 0; i < 8; i++) {
                int d0 = gj * 4 + i * 16;
                *(half2*)(dr + d0)     = __floats2half2_rn(xreg[i].x, xreg[i].y);
                *(half2*)(dr + d0 + 2) = __floats2half2_rn(xreg[i].z, xreg[i].w);
            }
            if (gj == 0) sDst[grow] = dreg;
        }
        __syncthreads();

        // L1: [64,128]@[128,64]
        {
            float c[4][4] = {};
            wgemm<DD, XSH, XSH, 4>(sX, sW1T, mrow, nc4, g, tig, c);
            epi_store<4>(c, sH1, HSH, sb1, mrow, nc4, g, tig);
        }
        __syncthreads();

        // L2: [64,64]@[64,64]
        {
            float c[4][4] = {};
            wgemm<HH, HSH, HSH, 4>(sH1, sW2T, mrow, nc4, g, tig, c);
            epi_store<4>(c, sH2, HSH, sb2, mrow, nc4, g, tig);
        }
        __syncthreads();

        // L3: [64,64]@[64,128] -> msg into sX
        {
            float c[8][4] = {};
            wgemm<HH, HSH, HSH, 8>(sH2, sW3T, mrow, nc8, g, tig, c);
            epi_store<8>(c, sX, XSH, sb3, mrow, nc8, g, tig);
        }
        __syncthreads();

        // prefetch next tile's gather chain; hides behind L4 + reductions
        if (tile + nb < ntiles) prefetch(tile + nb);

        // L4: [64,128]@[128,64] -> reductions into g_acc
        {
            float c[4][4] = {};
            wgemm<DD, XSH, XSH, 4>(sX, sWnT, mrow, nc4, g, tig, c);
            int d0 = sDst[mrow + g];
            int d1 = sDst[mrow + g + 8];
            #pragma unroll
            for (int j = 0; j < 4; j++) {
                int col = nc4 + j * 8 + 2 * tig;
                if (d0 >= 0) red2(g_acc + (long)d0 * HH + col, c[j][0], c[j][1]);
                if (d1 >= 0) red2(g_acc + (long)d1 * HH + col, c[j][2], c[j][3]);
            }
        }
    }
}

// ---------------------------------------------------------------------------
// Node kernel with cross-tile prefetch of x and g_acc.
// ---------------------------------------------------------------------------
__global__ __launch_bounds__(NTHREADS, 2)
void node_kernel(const float* __restrict__ nf,
                 const float* __restrict__ Wn1, const float* __restrict__ bn1,
                 const float* __restrict__ Wn2, const float* __restrict__ bn2,
                 const float* __restrict__ Wn3, const float* __restrict__ bn3,
                 float* __restrict__ out) {
    extern __shared__ __align__(16) char smraw[];
    __half* sW1T = (__half*)(smraw + N_W1T);
    __half* sW2T = (__half*)(smraw + N_W2T);
    __half* sW3T = (__half*)(smraw + N_W3T);
    __half* sX   = (__half*)(smraw + N_SX);
    __half* sH1  = (__half*)(smraw + N_SH1);
    __half* sH2  = (__half*)(smraw + N_SH2);
    float*  sb1  = (float*)(smraw + N_SB1);
    float*  sb2  = (float*)(smraw + N_SB2);
    float*  sb3  = (float*)(smraw + N_SB3);

    const int t = threadIdx.x;
    load_wT_128x64(Wn1, sW1T, t);
    load_wT_64x64(Wn2, sW2T, t);
    load_wT_64x128(Wn3, sW3T, t);
    if (t < HH) { sb1[t] = bn1[t]; sb2[t] = bn2[t]; }
    if (t < DD) sb3[t] = bn3[t];

    const int ntiles = (NN + TE - 1) / TE;
    const int lane = t & 31, w = t >> 5;
    const int g = lane >> 2, tig = lane & 3;
    const int mrow = (w & 3) * 16;
    const int nc4  = (w >> 2) * 32;
    const int nc8  = (w >> 2) * 64;
    const int grow = t >> 2, gj = t & 3;

    float4 xreg[8];
    float2 ga[4][2];

    auto prefetch = [&](int tl) {
        const int n = tl * TE + grow;
        if (n < NN) {
            const float* xr = nf + (long)n * DD;
            #pragma unroll
            for (int i = 0; i < 8; i++)
                xreg[i] = *(const float4*)(xr + gj * 4 + i * 16);
        } else {
            #pragma unroll
            for (int i = 0; i < 8; i++)
                xreg[i] = make_float4(0.f, 0.f, 0.f, 0.f);
        }
        const int n0 = tl * TE + mrow + g;
        const int n1 = n0 + 8;
        #pragma unroll
        for (int j = 0; j < 4; j++) {
            int col = nc4 + j * 8 + 2 * tig;
            ga[j][0] = (n0 < NN) ? *(const float2*)(g_acc + (long)n0 * HH + col)
                                 : make_float2(0.f, 0.f);
            ga[j][1] = (n1 < NN) ? *(const float2*)(g_acc + (long)n1 * HH + col)
                                 : make_float2(0.f, 0.f);
        }
    };

    if (blockIdx.x < ntiles) prefetch(blockIdx.x);

    for (int tile = blockIdx.x; tile < ntiles; tile += gridDim.x) {
        const int base = tile * TE;
        __syncthreads();            // sX free; also weights on iter 0
        {
            __half* dr = sX + grow * XSH;
            #pragma unroll
            for (int i = 0; i < 8; i++) {
                int d0 = gj * 4 + i * 16;
                *(half2*)(dr + d0) = __floats2half2_rn(fmaxf(xreg[i].x, 0.f),
                                                       fmaxf(xreg[i].y, 0.f));
                *(half2*)(dr + d0 + 2) = __floats2half2_rn(fmaxf(xreg[i].z, 0.f),
                                                           fmaxf(xreg[i].w, 0.f));
            }
        }
        __syncthreads();

        const int n0 = base + mrow + g;
        const int n1 = n0 + 8;

        // L1 + g_acc (prefetched) + bias
        {
            float c[4][4] = {};
            wgemm<DD, XSH, XSH, 4>(sX, sW1T, mrow, nc4, g, tig, c);
            #pragma unroll
            for (int j = 0; j < 4; j++) {
                int col = nc4 + j * 8 + 2 * tig;
                float b0 = sb1[col], b1 = sb1[col + 1];
                *(half2*)(sH1 + (mrow + g) * HSH + col) =
                    (n0 < NN) ? __floats2half2_rn(fmaxf(c[j][0] + ga[j][0].x + b0, 0.f),
                                                  fmaxf(c[j][1] + ga[j][0].y + b1, 0.f))
                              : __floats2half2_rn(0.f, 0.f);
                *(half2*)(sH1 + (mrow + g + 8) * HSH + col) =
                    (n1 < NN) ? __floats2half2_rn(fmaxf(c[j][2] + ga[j][1].x + b0, 0.f),
                                                  fmaxf(c[j][3] + ga[j][1].y + b1, 0.f))
                              : __floats2half2_rn(0.f, 0.f);
            }
        }
        __syncthreads();

        // L2
        {
            float c[4][4] = {};
            wgemm<HH, HSH, HSH, 4>(sH1, sW2T, mrow, nc4, g, tig, c);
            epi_store<4>(c, sH2, HSH, sb2, mrow, nc4, g, tig);
        }
        __syncthreads();

        // prefetch next tile (hides behind L3 + output stores)
        if (tile + gridDim.x < ntiles) prefetch(tile + gridDim.x);

        // L3 -> out (fp32)
        {
            float c[8][4] = {};
            wgemm<HH, HSH, HSH, 8>(sH2, sW3T, mrow, nc8, g, tig, c);
            #pragma unroll
            for (int j = 0; j < 8; j++) {
                int col = nc8 + j * 8 + 2 * tig;
                float b0 = sb3[col], b1 = sb3[col + 1];
                if (n0 < NN) {
                    float2 v; v.x = c[j][0] + b0; v.y = c[j][1] + b1;
                    *(float2*)(out + (long)n0 * DD + col) = v;
                }
                if (n1 < NN) {
                    float2 v; v.x = c[j][2] + b0; v.y = c[j][3] + b1;
                    *(float2*)(out + (long)n1 * DD + col) = v;
                }
            }
        }
    }
}

extern "C" void kernel_launch(void* const* d_in, const int* in_sizes, int n_in,
                              void* d_out, int out_size) {
    const float* nf   = (const float*)d_in[0];
    const int*   esrc = (const int*)d_in[1];
    const int*   edst = (const int*)d_in[2];
    const int*   etyp = (const int*)d_in[3];
    const float* Wr1  = (const float*)d_in[4];
    const float* br1  = (const float*)d_in[5];
    const float* Wr2  = (const float*)d_in[6];
    const float* br2  = (const float*)d_in[7];
    const float* Wr3  = (const float*)d_in[8];
    const float* br3  = (const float*)d_in[9];
    const float* Wn1  = (const float*)d_in[10];
    const float* bn1  = (const float*)d_in[11];
    const float* Wn2  = (const float*)d_in[12];
    const float* bn2  = (const float*)d_in[13];
    const float* Wn3  = (const float*)d_in[14];
    const float* bn3  = (const float*)d_in[15];
    float* out = (float*)d_out;

    cudaFuncSetAttribute(edge_kernel, cudaFuncAttributeMaxDynamicSharedMemorySize, E_TOTAL);
    cudaFuncSetAttribute(node_kernel, cudaFuncAttributeMaxDynamicSharedMemorySize, N_TOTAL);

    void* accp = nullptr; void* cntp = nullptr;
    cudaGetSymbolAddress(&accp, g_acc);
    cudaGetSymbolAddress(&cntp, g_cnt);
    cudaMemsetAsync(accp, 0, (size_t)NN * HH * sizeof(float));
    cudaMemsetAsync(cntp, 0, RR * sizeof(int));

    bin_kernel<<<(NE + NTHREADS - 1) / NTHREADS, NTHREADS>>>(etyp);
    edge_kernel<<<2 * NSM, NTHREADS, E_TOTAL>>>(nf, esrc, edst,
                                                Wr1, br1, Wr2, br2, Wr3, br3, Wn1);
    node_kernel<<<2 * NSM, NTHREADS, N_TOTAL>>>(nf, Wn1, bn1, Wn2, bn2, Wn3, bn3, out);
}

// round 15
// speedup vs baseline: 1.1478x; 1.0020x over previous
#include <cuda_runtime.h>
#include <cuda_fp16.h>
#include <cstdint>

#define NN 50000
#define NE 200000
#define DD 128
#define RR 4
#define HH 64
#define TE 64            // rows (edges/nodes) per tile (M)
#define XSH 136          // stride (halves) for 128-wide buffers; /2 = 68 ≡ 4 mod 32
#define HSH 72           // stride (halves) for 64-wide buffers;   /2 = 36 ≡ 4 mod 32
#define NTHREADS 256
#define NSM 152

__device__ float g_acc[NN * HH];
__device__ int   g_bucket[RR * NE];
__device__ int   g_cnt[RR];

__global__ void bin_kernel(const int* __restrict__ etype) {
    __shared__ int s_cnt[RR];
    __shared__ int s_base[RR];
    int t = threadIdx.x;
    if (t < RR) s_cnt[t] = 0;
    __syncthreads();
    int e = blockIdx.x * blockDim.x + t;
    int r = -1, pos = 0;
    if (e < NE) { r = etype[e]; pos = atomicAdd(&s_cnt[r], 1); }
    __syncthreads();
    if (t < RR) s_base[t] = atomicAdd(&g_cnt[t], s_cnt[t]);
    __syncthreads();
    if (r >= 0) g_bucket[r * NE + s_base[r] + pos] = e;
}

// ---- helpers ----------------------------------------------------------------
__device__ __forceinline__ uint32_t smem_u32(const void* p) {
    uint32_t a;
    asm("{ .reg .u64 tmp; cvta.to.shared.u64 tmp, %1; cvt.u32.u64 %0, tmp; }"
        : "=r"(a) : "l"(p));
    return a;
}
__device__ __forceinline__ void mma_f16(float c[4], uint32_t a0, uint32_t a1,
                                        uint32_t a2, uint32_t a3,
                                        uint32_t b0, uint32_t b1) {
    asm volatile(
        "mma.sync.aligned.m16n8k16.row.col.f32.f16.f16.f32 "
        "{%0,%1,%2,%3}, {%4,%5,%6,%7}, {%8,%9}, {%0,%1,%2,%3};"
        : "+f"(c[0]), "+f"(c[1]), "+f"(c[2]), "+f"(c[3])
        : "r"(a0), "r"(a1), "r"(a2), "r"(a3), "r"(b0), "r"(b1));
}
__device__ __forceinline__ void red2(float* p, float x, float y) {
    asm volatile("red.global.add.v2.f32 [%0], {%1, %2};"
                 :: "l"(p), "f"(x), "f"(y) : "memory");
}

// Vectorized transposed weight loaders (R14 winner).
__device__ __forceinline__ void load_wT_128x64(const float* __restrict__ src,
                                               __half* __restrict__ dst, int t) {
    const int h = t & 63, dg = (t >> 6) & 3;
    #pragma unroll
    for (int base = 0; base < DD; base += 16) {
        int d0 = base + dg * 4;
        float a0 = src[(d0 + 0) * HH + h];
        float a1 = src[(d0 + 1) * HH + h];
        float a2 = src[(d0 + 2) * HH + h];
        float a3 = src[(d0 + 3) * HH + h];
        *(half2*)(dst + h * XSH + d0)     = __floats2half2_rn(a0, a1);
        *(half2*)(dst + h * XSH + d0 + 2) = __floats2half2_rn(a2, a3);
    }
}
__device__ __forceinline__ void load_wT_64x64(const float* __restrict__ src,
                                              __half* __restrict__ dst, int t) {
    const int h = t & 63, kg = (t >> 6) & 3;
    #pragma unroll
    for (int base = 0; base < HH; base += 16) {
        int k0 = base + kg * 4;
        float a0 = src[(k0 + 0) * HH + h];
        float a1 = src[(k0 + 1) * HH + h];
        float a2 = src[(k0 + 2) * HH + h];
        float a3 = src[(k0 + 3) * HH + h];
        *(half2*)(dst + h * HSH + k0)     = __floats2half2_rn(a0, a1);
        *(half2*)(dst + h * HSH + k0 + 2) = __floats2half2_rn(a2, a3);
    }
}
__device__ __forceinline__ void load_wT_64x128(const float* __restrict__ src,
                                               __half* __restrict__ dst, int t) {
    const int d = t & 127, kg = (t >> 7) & 1;
    #pragma unroll
    for (int base = 0; base < HH; base += 8) {
        int k0 = base + kg * 4;
        float a0 = src[(k0 + 0) * DD + d];
        float a1 = src[(k0 + 1) * DD + d];
        float a2 = src[(k0 + 2) * DD + d];
        float a3 = src[(k0 + 3) * DD + d];
        *(half2*)(dst + d * HSH + k0)     = __floats2half2_rn(a0, a1);
        *(half2*)(dst + d * HSH + k0 + 2) = __floats2half2_rn(a2, a3);
    }
}

// Warp GEMM with ldmatrix.x4 A-fragment loads.
// act: [M][AST] halves, wT: [N][KS] halves. Warp: rows mrow0..+15,
// cols ncol0..+8*NCH-1. Lane address: row mrow0+(lane&15), k-off (lane>>4)*8.
template<int K, int AST, int KS, int NCH>
__device__ __forceinline__ void wgemm(const __half* __restrict__ act,
                                      const __half* __restrict__ wT,
                                      int mrow0, int ncol0, int lane,
                                      int g, int tig, float c[NCH][4]) {
    uint32_t aaddr = smem_u32(act + (mrow0 + (lane & 15)) * AST + ((lane >> 4) << 3));
    #pragma unroll
    for (int k0 = 0; k0 < K; k0 += 16) {
        uint32_t a0, a1, a2, a3;
        asm volatile("ldmatrix.sync.aligned.m8n8.x4.shared.b16 {%0,%1,%2,%3}, [%4];"
                     : "=r"(a0), "=r"(a1), "=r"(a2), "=r"(a3)
                     : "r"(aaddr + (uint32_t)(k0 * 2)));
        #pragma unroll
        for (int j = 0; j < NCH; j++) {
            const __half* wn = wT + (ncol0 + j * 8 + g) * KS + k0 + 2 * tig;
            uint32_t b0 = *(const uint32_t*)(wn);
            uint32_t b1 = *(const uint32_t*)(wn + 8);
            mma_f16(c[j], a0, a1, a2, a3, b0, b1);
        }
    }
}

// Epilogue: bias + relu + fp16-round, store half2 to smem [M][OST].
template<int NCH>
__device__ __forceinline__ void epi_store(float c[NCH][4], __half* outb, int OST,
                                          const float* bias, int mrow0, int ncol0,
                                          int g, int tig) {
    #pragma unroll
    for (int j = 0; j < NCH; j++) {
        int col = ncol0 + j * 8 + 2 * tig;
        float b0 = bias[col], b1 = bias[col + 1];
        *(half2*)(outb + (mrow0 + g) * OST + col) =
            __floats2half2_rn(fmaxf(c[j][0] + b0, 0.f), fmaxf(c[j][1] + b1, 0.f));
        *(half2*)(outb + (mrow0 + g + 8) * OST + col) =
            __floats2half2_rn(fmaxf(c[j][2] + b0, 0.f), fmaxf(c[j][3] + b1, 0.f));
    }
}

// SMEM layouts (byte offsets)
#define E_W1T 0
#define E_W2T (E_W1T + HH * XSH * 2)
#define E_W3T (E_W2T + HH * HSH * 2)
#define E_WNT (E_W3T + DD * HSH * 2)
#define E_SX  (E_WNT + HH * XSH * 2)
#define E_SH1 (E_SX + TE * XSH * 2)
#define E_SH2 (E_SH1 + TE * HSH * 2)
#define E_SB1 (E_SH2 + TE * HSH * 2)
#define E_SB2 (E_SB1 + HH * 4)
#define E_SB3 (E_SB2 + HH * 4)
#define E_DST (E_SB3 + DD * 4)
#define E_TOTAL (E_DST + TE * 4)          // ~99.6 KB -> occ 2

#define N_W1T 0
#define N_W2T (N_W1T + HH * XSH * 2)
#define N_W3T (N_W2T + HH * HSH * 2)
#define N_SX  (N_W3T + DD * HSH * 2)
#define N_SH1 (N_SX + TE * XSH * 2)
#define N_SH2 (N_SH1 + TE * HSH * 2)
#define N_SB1 (N_SH2 + TE * HSH * 2)
#define N_SB2 (N_SB1 + HH * 4)
#define N_SB3 (N_SB2 + HH * 4)
#define N_TOTAL (N_SB3 + DD * 4)          // 81920 B -> occ 2

// ---------------------------------------------------------------------------
// Edge kernel with cross-tile prefetch of the gather chain.
// ---------------------------------------------------------------------------
__global__ __launch_bounds__(NTHREADS, 2)
void edge_kernel(const float* __restrict__ nf,
                 const int* __restrict__ esrc, const int* __restrict__ edst,
                 const float* __restrict__ Wr1, const float* __restrict__ br1,
                 const float* __restrict__ Wr2, const float* __restrict__ br2,
                 const float* __restrict__ Wr3, const float* __restrict__ br3,
                 const float* __restrict__ Wn1) {
    extern __shared__ __align__(16) char smraw[];
    __half* sW1T = (__half*)(smraw + E_W1T);   // [64][XSH]  W1^T
    __half* sW2T = (__half*)(smraw + E_W2T);   // [64][HSH]
    __half* sW3T = (__half*)(smraw + E_W3T);   // [128][HSH]
    __half* sWnT = (__half*)(smraw + E_WNT);   // [64][XSH]
    __half* sX   = (__half*)(smraw + E_SX);    // [64][XSH]  x / msg
    __half* sH1  = (__half*)(smraw + E_SH1);   // [64][HSH]
    __half* sH2  = (__half*)(smraw + E_SH2);   // [64][HSH]
    float*  sb1  = (float*)(smraw + E_SB1);
    float*  sb2  = (float*)(smraw + E_SB2);
    float*  sb3  = (float*)(smraw + E_SB3);
    int*    sDst = (int*)(smraw + E_DST);

    const int t     = threadIdx.x;
    const int rel   = blockIdx.x & (RR - 1);
    const int bslot = blockIdx.x >> 2;
    const int nb    = gridDim.x >> 2;

    load_wT_128x64(Wr1 + rel * DD * HH, sW1T, t);
    load_wT_128x64(Wn1 + (1 + rel) * DD * HH, sWnT, t);
    load_wT_64x64(Wr2 + rel * HH * HH, sW2T, t);
    load_wT_64x128(Wr3 + rel * HH * DD, sW3T, t);
    if (t < HH) { sb1[t] = br1[rel * HH + t]; sb2[t] = br2[rel * HH + t]; }
    if (t < DD) { sb3[t] = br3[rel * DD + t]; }

    const int cnt    = g_cnt[rel];
    const int ntiles = (cnt + TE - 1) / TE;

    const int lane = t & 31, w = t >> 5;
    const int g = lane >> 2, tig = lane & 3;
    const int mrow = (w & 3) * 16;
    const int nc4  = (w >> 2) * 32;
    const int nc8  = (w >> 2) * 64;
    const int grow = t >> 2, gj = t & 3;
    const int* gb = g_bucket + rel * NE;

    float4 xreg[8];
    int dreg = -1;

    auto prefetch = [&](int tl) {
        int idxr = tl * TE + grow;
        int src = 0; dreg = -1;
        if (idxr < cnt) {
            int e = gb[idxr];
            src = esrc[e];
            dreg = edst[e];
        }
        const float* xp = nf + (long)src * DD;
        #pragma unroll
        for (int i = 0; i < 8; i++)
            xreg[i] = *(const float4*)(xp + gj * 4 + i * 16);
    };

    if (bslot < ntiles) prefetch(bslot);

    for (int tile = bslot; tile < ntiles; tile += nb) {
        __syncthreads();             // sX / sDst free (prev L4 done); weights on iter 0
        {
            __half* dr = sX + grow * XSH;
            #pragma unroll
            for (int i = 0; i < 8; i++) {
                int d0 = gj * 4 + i * 16;
                *(half2*)(dr + d0)     = __floats2half2_rn(xreg[i].x, xreg[i].y);
                *(half2*)(dr + d0 + 2) = __floats2half2_rn(xreg[i].z, xreg[i].w);
            }
            if (gj == 0) sDst[grow] = dreg;
        }
        __syncthreads();

        // L1: [64,128]@[128,64]
        {
            float c[4][4] = {};
            wgemm<DD, XSH, XSH, 4>(sX, sW1T, mrow, nc4, lane, g, tig, c);
            epi_store<4>(c, sH1, HSH, sb1, mrow, nc4, g, tig);
        }
        __syncthreads();

        // L2: [64,64]@[64,64]
        {
            float c[4][4] = {};
            wgemm<HH, HSH, HSH, 4>(sH1, sW2T, mrow, nc4, lane, g, tig, c);
            epi_store<4>(c, sH2, HSH, sb2, mrow, nc4, g, tig);
        }
        __syncthreads();

        // L3: [64,64]@[64,128] -> msg into sX
        {
            float c[8][4] = {};
            wgemm<HH, HSH, HSH, 8>(sH2, sW3T, mrow, nc8, lane, g, tig, c);
            epi_store<8>(c, sX, XSH, sb3, mrow, nc8, g, tig);
        }
        __syncthreads();

        // prefetch next tile's gather chain; hides behind L4 + reductions
        if (tile + nb < ntiles) prefetch(tile + nb);

        // L4: [64,128]@[128,64] -> reductions into g_acc
        {
            float c[4][4] = {};
            wgemm<DD, XSH, XSH, 4>(sX, sWnT, mrow, nc4, lane, g, tig, c);
            int d0 = sDst[mrow + g];
            int d1 = sDst[mrow + g + 8];
            #pragma unroll
            for (int j = 0; j < 4; j++) {
                int col = nc4 + j * 8 + 2 * tig;
                if (d0 >= 0) red2(g_acc + (long)d0 * HH + col, c[j][0], c[j][1]);
                if (d1 >= 0) red2(g_acc + (long)d1 * HH + col, c[j][2], c[j][3]);
            }
        }
    }
}

// ---------------------------------------------------------------------------
// Node kernel with cross-tile prefetch of x and g_acc.
// ---------------------------------------------------------------------------
__global__ __launch_bounds__(NTHREADS, 2)
void node_kernel(const float* __restrict__ nf,
                 const float* __restrict__ Wn1, const float* __restrict__ bn1,
                 const float* __restrict__ Wn2, const float* __restrict__ bn2,
                 const float* __restrict__ Wn3, const float* __restrict__ bn3,
                 float* __restrict__ out) {
    extern __shared__ __align__(16) char smraw[];
    __half* sW1T = (__half*)(smraw + N_W1T);
    __half* sW2T = (__half*)(smraw + N_W2T);
    __half* sW3T = (__half*)(smraw + N_W3T);
    __half* sX   = (__half*)(smraw + N_SX);
    __half* sH1  = (__half*)(smraw + N_SH1);
    __half* sH2  = (__half*)(smraw + N_SH2);
    float*  sb1  = (float*)(smraw + N_SB1);
    float*  sb2  = (float*)(smraw + N_SB2);
    float*  sb3  = (float*)(smraw + N_SB3);

    const int t = threadIdx.x;
    load_wT_128x64(Wn1, sW1T, t);
    load_wT_64x64(Wn2, sW2T, t);
    load_wT_64x128(Wn3, sW3T, t);
    if (t < HH) { sb1[t] = bn1[t]; sb2[t] = bn2[t]; }
    if (t < DD) sb3[t] = bn3[t];

    const int ntiles = (NN + TE - 1) / TE;
    const int lane = t & 31, w = t >> 5;
    const int g = lane >> 2, tig = lane & 3;
    const int mrow = (w & 3) * 16;
    const int nc4  = (w >> 2) * 32;
    const int nc8  = (w >> 2) * 64;
    const int grow = t >> 2, gj = t & 3;

    float4 xreg[8];
    float2 ga[4][2];

    auto prefetch = [&](int tl) {
        const int n = tl * TE + grow;
        if (n < NN) {
            const float* xr = nf + (long)n * DD;
            #pragma unroll
            for (int i = 0; i < 8; i++)
                xreg[i] = *(const float4*)(xr + gj * 4 + i * 16);
        } else {
            #pragma unroll
            for (int i = 0; i < 8; i++)
                xreg[i] = make_float4(0.f, 0.f, 0.f, 0.f);
        }
        const int n0 = tl * TE + mrow + g;
        const int n1 = n0 + 8;
        #pragma unroll
        for (int j = 0; j < 4; j++) {
            int col = nc4 + j * 8 + 2 * tig;
            ga[j][0] = (n0 < NN) ? *(const float2*)(g_acc + (long)n0 * HH + col)
                                 : make_float2(0.f, 0.f);
            ga[j][1] = (n1 < NN) ? *(const float2*)(g_acc + (long)n1 * HH + col)
                                 : make_float2(0.f, 0.f);
        }
    };

    if (blockIdx.x < ntiles) prefetch(blockIdx.x);

    for (int tile = blockIdx.x; tile < ntiles; tile += gridDim.x) {
        const int base = tile * TE;
        __syncthreads();            // sX free; weights on iter 0
        {
            __half* dr = sX + grow * XSH;
            #pragma unroll
            for (int i = 0; i < 8; i++) {
                int d0 = gj * 4 + i * 16;
                *(half2*)(dr + d0) = __floats2half2_rn(fmaxf(xreg[i].x, 0.f),
                                                       fmaxf(xreg[i].y, 0.f));
                *(half2*)(dr + d0 + 2) = __floats2half2_rn(fmaxf(xreg[i].z, 0.f),
                                                           fmaxf(xreg[i].w, 0.f));
            }
        }
        __syncthreads();

        const int n0 = base + mrow + g;
        const int n1 = n0 + 8;

        // L1 + g_acc (prefetched) + bias
        {
            float c[4][4] = {};
            wgemm<DD, XSH, XSH, 4>(sX, sW1T, mrow, nc4, lane, g, tig, c);
            #pragma unroll
            for (int j = 0; j < 4; j++) {
                int col = nc4 + j * 8 + 2 * tig;
                float b0 = sb1[col], b1 = sb1[col + 1];
                *(half2*)(sH1 + (mrow + g) * HSH + col) =
                    (n0 < NN) ? __floats2half2_rn(fmaxf(c[j][0] + ga[j][0].x + b0, 0.f),
                                                  fmaxf(c[j][1] + ga[j][0].y + b1, 0.f))
                              : __floats2half2_rn(0.f, 0.f);
                *(half2*)(sH1 + (mrow + g + 8) * HSH + col) =
                    (n1 < NN) ? __floats2half2_rn(fmaxf(c[j][2] + ga[j][1].x + b0, 0.f),
                                                  fmaxf(c[j][3] + ga[j][1].y + b1, 0.f))
                              : __floats2half2_rn(0.f, 0.f);
            }
        }
        __syncthreads();

        // L2
        {
            float c[4][4] = {};
            wgemm<HH, HSH, HSH, 4>(sH1, sW2T, mrow, nc4, lane, g, tig, c);
            epi_store<4>(c, sH2, HSH, sb2, mrow, nc4, g, tig);
        }
        __syncthreads();

        // prefetch next tile (hides behind L3 + output stores)
        if (tile + gridDim.x < ntiles) prefetch(tile + gridDim.x);

        // L3 -> out (fp32)
        {
            float c[8][4] = {};
            wgemm<HH, HSH, HSH, 8>(sH2, sW3T, mrow, nc8, lane, g, tig, c);
            #pragma unroll
            for (int j = 0; j < 8; j++) {
                int col = nc8 + j * 8 + 2 * tig;
                float b0 = sb3[col], b1 = sb3[col + 1];
                if (n0 < NN) {
                    float2 v; v.x = c[j][0] + b0; v.y = c[j][1] + b1;
                    *(float2*)(out + (long)n0 * DD + col) = v;
                }
                if (n1 < NN) {
                    float2 v; v.x = c[j][2] + b0; v.y = c[j][3] + b1;
                    *(float2*)(out + (long)n1 * DD + col) = v;
                }
            }
        }
    }
}

extern "C" void kernel_launch(void* const* d_in, const int* in_sizes, int n_in,
                              void* d_out, int out_size) {
    const float* nf   = (const float*)d_in[0];
    const int*   esrc = (const int*)d_in[1];
    const int*   edst = (const int*)d_in[2];
    const int*   etyp = (const int*)d_in[3];
    const float* Wr1  = (const float*)d_in[4];
    const float* br1  = (const float*)d_in[5];
    const float* Wr2  = (const float*)d_in[6];
    const float* br2  = (const float*)d_in[7];
    const float* Wr3  = (const float*)d_in[8];
    const float* br3  = (const float*)d_in[9];
    const float* Wn1  = (const float*)d_in[10];
    const float* bn1  = (const float*)d_in[11];
    const float* Wn2  = (const float*)d_in[12];
    const float* bn2  = (const float*)d_in[13];
    const float* Wn3  = (const float*)d_in[14];
    const float* bn3  = (const float*)d_in[15];
    float* out = (float*)d_out;

    cudaFuncSetAttribute(edge_kernel, cudaFuncAttributeMaxDynamicSharedMemorySize, E_TOTAL);
    cudaFuncSetAttribute(node_kernel, cudaFuncAttributeMaxDynamicSharedMemorySize, N_TOTAL);

    void* accp = nullptr; void* cntp = nullptr;
    cudaGetSymbolAddress(&accp, g_acc);
    cudaGetSymbolAddress(&cntp, g_cnt);
    cudaMemsetAsync(accp, 0, (size_t)NN * HH * sizeof(float));
    cudaMemsetAsync(cntp, 0, RR * sizeof(int));

    bin_kernel<<<(NE + NTHREADS - 1) / NTHREADS, NTHREADS>>>(etyp);
    edge_kernel<<<2 * NSM, NTHREADS, E_TOTAL>>>(nf, esrc, edst,
                                                Wr1, br1, Wr2, br2, Wr3, br3, Wn1);
    node_kernel<<<2 * NSM, NTHREADS, N_TOTAL>>>(nf, Wn1, bn1, Wn2, bn2, Wn3, bn3, out);
}